// round 13
// baseline (speedup 1.0000x reference)
#include <cuda_runtime.h>
#include <cuda_bf16.h>
#include <stdint.h>

#define BATCH 2048
#define HW81  81
#define CDIM  512
#define HID   256
#define MPAD  96                  /* 81 rows padded to 6x16 */

// W pre-rounded to tf32 (fp32 bit patterns), [256][512]
__device__ float g_Wt[HID * CDIM];

// ---------------------------------------------------------------------------
// helpers
// ---------------------------------------------------------------------------
__device__ __forceinline__ uint32_t f2tf32(float f) {
    uint32_t u;
    asm("cvt.rna.tf32.f32 %0, %1;" : "=r"(u) : "f"(f));
    return u;
}

__device__ __forceinline__ uint32_t smem_u32(const void* p) {
    uint32_t a;
    asm("{ .reg .u64 t; cvta.to.shared.u64 t, %1; cvt.u32.u64 %0, t; }" : "=r"(a) : "l"(p));
    return a;
}

__device__ __forceinline__ void cp16(uint32_t dst, const void* src) {
    asm volatile("cp.async.cg.shared.global [%0], [%1], 16;" :: "r"(dst), "l"(src));
}

__device__ __forceinline__ void mma_tf32(float* c, uint32_t a0, uint32_t a1,
                                         uint32_t a2, uint32_t a3,
                                         uint32_t b0, uint32_t b1) {
    asm volatile(
        "mma.sync.aligned.m16n8k8.row.col.f32.tf32.tf32.f32 "
        "{%0,%1,%2,%3}, {%4,%5,%6,%7}, {%8,%9}, {%0,%1,%2,%3};\n"
        : "+f"(c[0]), "+f"(c[1]), "+f"(c[2]), "+f"(c[3])
        : "r"(a0), "r"(a1), "r"(a2), "r"(a3), "r"(b0), "r"(b1));
}

// rm(q,p): row in x-natural order of token q of patch p's attention view
__device__ __forceinline__ int rowmap(int q, int p) {
    return (3 * (q / 3) + p / 3) * 9 + 3 * (q % 3) + (p % 3);
}

// ---------------------------------------------------------------------------
// Kernel 0: round W to tf32 (RNA) once.
// ---------------------------------------------------------------------------
__global__ void wprep_kernel(const float* __restrict__ Wf) {
    int i = blockIdx.x * 512 + threadIdx.x;
    g_Wt[i] = __uint_as_float(f2tf32(Wf[i]));
}

// ---------------------------------------------------------------------------
// Fused kernel: one CTA == one batch.
//   Phase 1: Y[96,256] = Xb(pad) @ W^T + b via tf32 mma.sync.
//     K staged 16 at a time, THREE rotating cp.async stages -> prefetch for
//     stage it+2 is issued BEFORE the MMA loop of stage it (single barrier
//     per iteration; cp-issue + DMA overlap the tensor stream).
//   Phase 2: syrk + double softmax from smem-Y -> P[81].
//   Phase 3: out = P @ v (v = raw x pixels, L2-hot re-read).
// 256 threads = 8 warps (2M x 4N), warp tile 48x64.
// smem: 3 stages x 27.5KB = 84.5KB dyn (Y 83KB reuses it) -> 2 CTAs/SM.
// ---------------------------------------------------------------------------
#define KSTG      16
#define STRIDE    20                         /* 16 + 4 pad: conflict-free  */
#define STG_FL    ((MPAD + HID) * STRIDE)    /* 7040 floats per stage      */
#define OFF_B     (MPAD * STRIDE)            /* 1920: B rows after A rows  */
#define SMEM_FLOATS (3 * STG_FL)             /* 21120 floats = 84480 B     */

__global__ __launch_bounds__(256, 2)
void fused_kernel(const float* __restrict__ X, const float* __restrict__ bfc,
                  float* __restrict__ out)
{
    extern __shared__ __align__(16) float smem[];
    __shared__ float sBias[HID];
    __shared__ float sRed[8][45];
    __shared__ float sAttn[81];
    __shared__ float sB2[81];
    __shared__ float sP[81];

    const int b    = blockIdx.x;
    const int tid  = threadIdx.x;
    const int lane = tid & 31;
    const int warp = tid >> 5;
    const int wm   = warp >> 2;          // 0..1 (M)
    const int wn   = warp & 3;           // 0..3 (N)
    const uint32_t sbase = smem_u32(smem);

    const float* Xb = X + (size_t)b * (HW81 * CDIM);

    sBias[tid] = __ldg(bfc + tid);

    float acc[3][8][4];
#pragma unroll
    for (int a = 0; a < 3; a++)
#pragma unroll
        for (int c = 0; c < 8; c++)
#pragma unroll
            for (int d = 0; d < 4; d++) acc[a][c][d] = 0.f;

    // per stage: A 96x16 = 384 float4 (tid does 1, tid<128 a 2nd),
    //            B 256x16 = 1024 float4 (4/thread)
#define ISSUE_STAGE(STG, BUF)                                                \
    do {                                                                     \
        const int k0 = (STG) * KSTG;                                         \
        const uint32_t bof = sbase + (BUF) * (STG_FL * 4);                   \
        {                                                                    \
            int r = tid >> 2, j = (tid & 3) << 2;                            \
            cp16(bof + (r * STRIDE + j) * 4,                                 \
                 Xb + (size_t)r * CDIM + k0 + j);                            \
        }                                                                    \
        if (tid < 128) {                                                     \
            int f = 256 + tid;                                               \
            int r = f >> 2, j = (f & 3) << 2;                                \
            int rs = r < HW81 ? r : (HW81 - 1);                              \
            cp16(bof + (r * STRIDE + j) * 4,                                 \
                 Xb + (size_t)rs * CDIM + k0 + j);                           \
        }                                                                    \
        _Pragma("unroll")                                                    \
        for (int i = 0; i < 4; i++) {                                        \
            int f = i * 256 + tid;  /* 0..1023 */                            \
            int n = f >> 2, j = (f & 3) << 2;                                \
            cp16(bof + (OFF_B + n * STRIDE + j) * 4,                         \
                 g_Wt + (size_t)n * CDIM + k0 + j);                          \
        }                                                                    \
        asm volatile("cp.async.commit_group;" ::: "memory");                 \
    } while (0)

    ISSUE_STAGE(0, 0);
    ISSUE_STAGE(1, 1);

    const int ar = wm * 48 + (lane >> 2);
    const int ac = lane & 3;
    const int bn = wn * 64 + (lane >> 2);

    int bc = 0;                          // buffer of stage `it`
    for (int it = 0; it < 32; it++) {
        if (it < 31) asm volatile("cp.async.wait_group 1;" ::: "memory");
        else         asm volatile("cp.async.wait_group 0;" ::: "memory");
        __syncthreads();

        // prefetch stage it+2 into the buffer freed at iteration it-1;
        // overlaps the MMA loop below.
        if (it < 30) {
            int bn2 = bc + 2; if (bn2 >= 3) bn2 -= 3;
            ISSUE_STAGE(it + 2, bn2);
        }

        const float*    sA = smem + bc * STG_FL;
        const uint32_t* sB = (const uint32_t*)(smem + bc * STG_FL + OFF_B);

#pragma unroll
        for (int kk = 0; kk < 2; kk++) {
            const int c = kk * 8 + ac;
            uint32_t bf[8][2];
#pragma unroll
            for (int nt = 0; nt < 8; nt++) {
                bf[nt][0] = sB[(bn + nt * 8) * STRIDE + c];
                bf[nt][1] = sB[(bn + nt * 8) * STRIDE + c + 4];
            }
#pragma unroll
            for (int mt = 0; mt < 3; mt++) {
                const int r = ar + mt * 16;
                uint32_t a0 = f2tf32(sA[r * STRIDE + c]);
                uint32_t a1 = f2tf32(sA[(r + 8) * STRIDE + c]);
                uint32_t a2 = f2tf32(sA[r * STRIDE + c + 4]);
                uint32_t a3 = f2tf32(sA[(r + 8) * STRIDE + c + 4]);
#pragma unroll
                for (int nt = 0; nt < 8; nt++)
                    mma_tf32(acc[mt][nt], a0, a1, a2, a3, bf[nt][0], bf[nt][1]);
            }
        }

        bc = bc + 1; if (bc >= 3) bc -= 3;
    }

    // ---- write Y (rows < 81) + bias into smem, reusing staging ----
    __syncthreads();           // all warps done reading stage buffers
    float* sY = smem;          // [81][256] = 20736 floats <= 21120
#pragma unroll
    for (int nt = 0; nt < 8; nt++) {
        const int cc = wn * 64 + nt * 8 + ((lane & 3) << 1);
        const float b0 = sBias[cc];
        const float b1 = sBias[cc + 1];
#pragma unroll
        for (int mt = 0; mt < 3; mt++) {
            const int r = ar + mt * 16;
            if (r < HW81) {
                sY[r * HID + cc]     = acc[mt][nt][0] + b0;
                sY[r * HID + cc + 1] = acc[mt][nt][1] + b1;
            }
            if (r + 8 < HW81) {
                sY[(r + 8) * HID + cc]     = acc[mt][nt][2] + b0;
                sY[(r + 8) * HID + cc + 1] = acc[mt][nt][3] + b1;
            }
        }
    }
    __syncthreads();

    // ---- syrk: attn[n,m] = (1/48) sum_{p,h} Y[rm(n,p),h] Y[rm(m,p),h] ----
    {
        float sa[45];
#pragma unroll
        for (int i = 0; i < 45; i++) sa[i] = 0.f;
#pragma unroll
        for (int p = 0; p < 9; p++) {
            float z[9];
#pragma unroll
            for (int q = 0; q < 9; q++)
                z[q] = sY[rowmap(q, p) * HID + tid];
            int cidx = 0;
#pragma unroll
            for (int n = 0; n < 9; n++)
#pragma unroll
                for (int m = n; m < 9; m++)
                    sa[cidx++] += z[n] * z[m];
        }
#pragma unroll
        for (int i = 0; i < 45; i++) {
            float v = sa[i];
#pragma unroll
            for (int o = 16; o > 0; o >>= 1) v += __shfl_xor_sync(0xffffffffu, v, o);
            if (lane == 0) sRed[warp][i] = v;
        }
    }
    __syncthreads();

    if (tid < 45) {
        float s = 0.f;
#pragma unroll
        for (int w = 0; w < 8; w++) s += sRed[w][tid];
        int n = 0, m = tid;
        while (m >= 9 - n) { m -= (9 - n); n++; }
        m += n;
        float v = s * (1.0f / 48.0f);     // (hidden*P)^-0.5 = 1/sqrt(2304)
        if (n == m) v -= 100.0f;          // diagonal self-suppression
        sAttn[n * 9 + m] = v;
        sAttn[m * 9 + n] = v;
    }
    __syncthreads();

    if (tid < 81) {
        int n = tid / 9, k = tid % 9;
        float s = 0.f;
#pragma unroll
        for (int m = 0; m < 9; m++) s += sAttn[n * 9 + m] * sAttn[k * 9 + m];
        sB2[tid] = s * (1.0f / 3.0f);
    }
    __syncthreads();

    if (tid < 9) {
        int n = tid;
        float mx = -1e30f;
#pragma unroll
        for (int k = 0; k < 9; k++) mx = fmaxf(mx, sB2[n * 9 + k]);
        float e[9]; float se = 0.f;
#pragma unroll
        for (int k = 0; k < 9; k++) { e[k] = expf(sB2[n * 9 + k] - mx); se += e[k]; }
        float inv = 1.0f / se;
        float L[9]; float mx2 = -1e30f;
#pragma unroll
        for (int k = 0; k < 9; k++) {
            L[k] = sAttn[n * 9 + k] + e[k] * inv;
            mx2 = fmaxf(mx2, L[k]);
        }
        float e2[9]; float s2 = 0.f;
#pragma unroll
        for (int k = 0; k < 9; k++) { e2[k] = expf(L[k] - mx2); s2 += e2[k]; }
        float inv2 = 1.0f / s2;
#pragma unroll
        for (int k = 0; k < 9; k++) sP[n * 9 + k] = e2[k] * inv2;
    }
    __syncthreads();

    // ---- epilogue: out[n,p,c] = sum_m P[n,m] * x[rm(m,p),c] ----
    const float2* Xb2 = (const float2*)Xb;                       // [81][256]
    float2*       Ob  = (float2*)out + (size_t)b * (HW81 * 256);

#pragma unroll
    for (int p = 0; p < 9; p++) {
        float2 v[9];
#pragma unroll
        for (int m = 0; m < 9; m++)
            v[m] = Xb2[rowmap(m, p) * 256 + tid];
#pragma unroll
        for (int n = 0; n < 9; n++) {
            float2 o = make_float2(0.f, 0.f);
#pragma unroll
            for (int m = 0; m < 9; m++) {
                float w = sP[n * 9 + m];
                o.x += w * v[m].x;
                o.y += w * v[m].y;
            }
            Ob[rowmap(n, p) * 256 + tid] = o;
        }
    }
}

// ---------------------------------------------------------------------------
extern "C" void kernel_launch(void* const* d_in, const int* in_sizes, int n_in,
                              void* d_out, int out_size)
{
    const float* x   = (const float*)d_in[0];   // [2048, 9, 9, 512] fp32
    const float* Wf  = (const float*)d_in[1];   // [256, 512] fp32
    const float* bfc = (const float*)d_in[2];   // [256] fp32
    float* out = (float*)d_out;

    static bool init = false;
    if (!init) {
        cudaFuncSetAttribute(fused_kernel,
                             cudaFuncAttributeMaxDynamicSharedMemorySize,
                             SMEM_FLOATS * 4);
        init = true;
    }

    wprep_kernel<<<256, 512>>>(Wf);
    fused_kernel<<<BATCH, 256, SMEM_FLOATS * 4>>>(x, bfc, out);
}

// round 14
// speedup vs baseline: 1.0453x; 1.0453x over previous
#include <cuda_runtime.h>
#include <cuda_bf16.h>
#include <stdint.h>

#define BATCH 2048
#define HW81  81
#define CDIM  512
#define HID   256
#define MPAD  96                  /* 81 rows padded to 6x16 */

// W pre-rounded to tf32 (fp32 bit patterns), [256][512]
__device__ float g_Wt[HID * CDIM];

// ---------------------------------------------------------------------------
// helpers
// ---------------------------------------------------------------------------
__device__ __forceinline__ uint32_t f2tf32(float f) {
    uint32_t u;
    asm("cvt.rna.tf32.f32 %0, %1;" : "=r"(u) : "f"(f));
    return u;
}

__device__ __forceinline__ uint32_t smem_u32(const void* p) {
    uint32_t a;
    asm("{ .reg .u64 t; cvta.to.shared.u64 t, %1; cvt.u32.u64 %0, t; }" : "=r"(a) : "l"(p));
    return a;
}

__device__ __forceinline__ void cp16(uint32_t dst, const void* src) {
    asm volatile("cp.async.cg.shared.global [%0], [%1], 16;" :: "r"(dst), "l"(src));
}

__device__ __forceinline__ void mma_tf32(float* c, uint32_t a0, uint32_t a1,
                                         uint32_t a2, uint32_t a3,
                                         uint32_t b0, uint32_t b1) {
    asm volatile(
        "mma.sync.aligned.m16n8k8.row.col.f32.tf32.tf32.f32 "
        "{%0,%1,%2,%3}, {%4,%5,%6,%7}, {%8,%9}, {%0,%1,%2,%3};\n"
        : "+f"(c[0]), "+f"(c[1]), "+f"(c[2]), "+f"(c[3])
        : "r"(a0), "r"(a1), "r"(a2), "r"(a3), "r"(b0), "r"(b1));
}

// rm(q,p): row in x-natural order of token q of patch p's attention view
__device__ __forceinline__ int rowmap(int q, int p) {
    return (3 * (q / 3) + p / 3) * 9 + 3 * (q % 3) + (p % 3);
}

// ---------------------------------------------------------------------------
// Kernel 0: round W to tf32 (RNA) once.
// ---------------------------------------------------------------------------
__global__ void wprep_kernel(const float* __restrict__ Wf) {
    int i = blockIdx.x * 512 + threadIdx.x;
    g_Wt[i] = __uint_as_float(f2tf32(Wf[i]));
}

// ---------------------------------------------------------------------------
// Fused kernel: one CTA == one batch.
//   Phase 1: Y[96,256] = Xb(pad) @ W^T + b via tf32 mma.sync.
//     (R12 mainloop: K staged 32 at a time, 2 cp.async stages — best measured)
//   Phase 2: syrk + double softmax from smem-Y -> P[81] (stride-12 packed).
//   Phase 3: out = P @ v, software-pipelined LDG prefetch of v.
// 256 threads = 8 warps (2M x 4N), warp tile 48x64.
// smem: staging 101376B dyn (Y 83KB reuses it), 2 CTAs/SM.
// ---------------------------------------------------------------------------
#define KSTG     32
#define STRIDE   36
#define OFF_A0   0
#define OFF_B0   (MPAD * STRIDE)                 /* 3456  */
#define OFF_A1   (OFF_B0 + HID * STRIDE)         /* 12672 */
#define OFF_B1   (OFF_A1 + MPAD * STRIDE)        /* 16128 */
#define SMEM_FLOATS (OFF_B1 + HID * STRIDE)      /* 25344 floats = 101376 B */

__global__ __launch_bounds__(256, 2)
void fused_kernel(const float* __restrict__ X, const float* __restrict__ bfc,
                  float* __restrict__ out)
{
    extern __shared__ __align__(16) float smem[];
    __shared__ float sBias[HID];
    __shared__ float sRed[8][45];
    __shared__ float sAttn[81];
    __shared__ float sB2[81];
    __shared__ __align__(16) float sPp[9 * 12];   /* P rows padded to 12 */

    const int b    = blockIdx.x;
    const int tid  = threadIdx.x;
    const int lane = tid & 31;
    const int warp = tid >> 5;
    const int wm   = warp >> 2;          // 0..1 (M)
    const int wn   = warp & 3;           // 0..3 (N)
    const uint32_t sbase = smem_u32(smem);

    const float* Xb = X + (size_t)b * (HW81 * CDIM);

    sBias[tid] = __ldg(bfc + tid);

    float acc[3][8][4];
#pragma unroll
    for (int a = 0; a < 3; a++)
#pragma unroll
        for (int c = 0; c < 8; c++)
#pragma unroll
            for (int d = 0; d < 4; d++) acc[a][c][d] = 0.f;

    // per stage: A 96x32 = 768 float4 (3/thread, rows>=81 clamp),
    //            B 256x32 = 2048 float4 (8/thread)
#define ISSUE_STAGE(IT, OFFA, OFFB)                                          \
    do {                                                                     \
        const int k0 = (IT) * KSTG;                                          \
        _Pragma("unroll")                                                    \
        for (int i = 0; i < 3; i++) {                                        \
            int f = i * 256 + tid;  /* 0..767 */                             \
            int r = f >> 3, j = (f & 7) << 2;                                \
            int rs = r < HW81 ? r : (HW81 - 1);                              \
            cp16(sbase + ((OFFA) + r * STRIDE + j) * 4,                     \
                 Xb + (size_t)rs * CDIM + k0 + j);                          \
        }                                                                    \
        _Pragma("unroll")                                                    \
        for (int i = 0; i < 8; i++) {                                        \
            int f = i * 256 + tid;  /* 0..2047 */                            \
            int n = f >> 3, j = (f & 7) << 2;                                \
            cp16(sbase + ((OFFB) + n * STRIDE + j) * 4,                     \
                 g_Wt + (size_t)n * CDIM + k0 + j);                         \
        }                                                                    \
        asm volatile("cp.async.commit_group;" ::: "memory");                 \
    } while (0)

    ISSUE_STAGE(0, OFF_A0, OFF_B0);
    ISSUE_STAGE(1, OFF_A1, OFF_B1);

    const int ar = wm * 48 + (lane >> 2);
    const int ac = lane & 3;
    const int bn = wn * 64 + (lane >> 2);

    for (int it = 0; it < 16; it++) {
        if (it < 15) asm volatile("cp.async.wait_group 1;" ::: "memory");
        else         asm volatile("cp.async.wait_group 0;" ::: "memory");
        __syncthreads();

        const float*    sA = smem + ((it & 1) ? OFF_A1 : OFF_A0);
        const uint32_t* sB = (const uint32_t*)(smem + ((it & 1) ? OFF_B1 : OFF_B0));

#pragma unroll
        for (int kk = 0; kk < 4; kk++) {
            const int c = kk * 8 + ac;
            uint32_t bf[8][2];
#pragma unroll
            for (int nt = 0; nt < 8; nt++) {
                bf[nt][0] = sB[(bn + nt * 8) * STRIDE + c];
                bf[nt][1] = sB[(bn + nt * 8) * STRIDE + c + 4];
            }
#pragma unroll
            for (int mt = 0; mt < 3; mt++) {
                const int r = ar + mt * 16;
                uint32_t a0 = f2tf32(sA[r * STRIDE + c]);
                uint32_t a1 = f2tf32(sA[(r + 8) * STRIDE + c]);
                uint32_t a2 = f2tf32(sA[r * STRIDE + c + 4]);
                uint32_t a3 = f2tf32(sA[(r + 8) * STRIDE + c + 4]);
#pragma unroll
                for (int nt = 0; nt < 8; nt++)
                    mma_tf32(acc[mt][nt], a0, a1, a2, a3, bf[nt][0], bf[nt][1]);
            }
        }
        __syncthreads();

        if (it < 14) {
            if (it & 1) ISSUE_STAGE(it + 2, OFF_A1, OFF_B1);
            else        ISSUE_STAGE(it + 2, OFF_A0, OFF_B0);
        }
    }

    // ---- write Y (rows < 81) + bias into smem, reusing staging ----
    __syncthreads();           // all MMAs done reading stage buffers
    float* sY = smem;          // [81][256] = 20736 floats <= 25344
#pragma unroll
    for (int nt = 0; nt < 8; nt++) {
        const int cc = wn * 64 + nt * 8 + ((lane & 3) << 1);
        const float b0 = sBias[cc];
        const float b1 = sBias[cc + 1];
#pragma unroll
        for (int mt = 0; mt < 3; mt++) {
            const int r = ar + mt * 16;
            if (r < HW81) {
                sY[r * HID + cc]     = acc[mt][nt][0] + b0;
                sY[r * HID + cc + 1] = acc[mt][nt][1] + b1;
            }
            if (r + 8 < HW81) {
                sY[(r + 8) * HID + cc]     = acc[mt][nt][2] + b0;
                sY[(r + 8) * HID + cc + 1] = acc[mt][nt][3] + b1;
            }
        }
    }
    __syncthreads();

    // ---- syrk: attn[n,m] = (1/48) sum_{p,h} Y[rm(n,p),h] Y[rm(m,p),h] ----
    {
        float sa[45];
#pragma unroll
        for (int i = 0; i < 45; i++) sa[i] = 0.f;

        float zz[2][9];
#pragma unroll
        for (int q = 0; q < 9; q++)
            zz[0][q] = sY[rowmap(q, 0) * HID + tid];

#pragma unroll
        for (int p = 0; p < 9; p++) {
            const int cur = p & 1;
            if (p < 8) {
#pragma unroll
                for (int q = 0; q < 9; q++)
                    zz[cur ^ 1][q] = sY[rowmap(q, p + 1) * HID + tid];
            }
            int cidx = 0;
#pragma unroll
            for (int n = 0; n < 9; n++)
#pragma unroll
                for (int m = n; m < 9; m++)
                    sa[cidx++] += zz[cur][n] * zz[cur][m];
        }
#pragma unroll
        for (int i = 0; i < 45; i++) {
            float v = sa[i];
#pragma unroll
            for (int o = 16; o > 0; o >>= 1) v += __shfl_xor_sync(0xffffffffu, v, o);
            if (lane == 0) sRed[warp][i] = v;
        }
    }
    __syncthreads();

    // ---- early prefetch of epilogue v for p=0 (independent of P) ----
    const float2* Xb2 = (const float2*)Xb;                       // [81][256]
    float2 v[2][9];
#pragma unroll
    for (int m = 0; m < 9; m++)
        v[0][m] = Xb2[rowmap(m, 0) * 256 + tid];

    if (tid < 45) {
        float s = 0.f;
#pragma unroll
        for (int w = 0; w < 8; w++) s += sRed[w][tid];
        int n = 0, m = tid;
        while (m >= 9 - n) { m -= (9 - n); n++; }
        m += n;
        float val = s * (1.0f / 48.0f);   // (hidden*P)^-0.5 = 1/sqrt(2304)
        if (n == m) val -= 100.0f;        // diagonal self-suppression
        sAttn[n * 9 + m] = val;
        sAttn[m * 9 + n] = val;
    }
    __syncthreads();

    if (tid < 81) {
        int n = tid / 9, k = tid % 9;
        float s = 0.f;
#pragma unroll
        for (int m = 0; m < 9; m++) s += sAttn[n * 9 + m] * sAttn[k * 9 + m];
        sB2[tid] = s * (1.0f / 3.0f);
    }
    __syncthreads();

    if (tid < 9) {
        int n = tid;
        float mx = -1e30f;
#pragma unroll
        for (int k = 0; k < 9; k++) mx = fmaxf(mx, sB2[n * 9 + k]);
        float e[9]; float se = 0.f;
#pragma unroll
        for (int k = 0; k < 9; k++) { e[k] = expf(sB2[n * 9 + k] - mx); se += e[k]; }
        float inv = 1.0f / se;
        float L[9]; float mx2 = -1e30f;
#pragma unroll
        for (int k = 0; k < 9; k++) {
            L[k] = sAttn[n * 9 + k] + e[k] * inv;
            mx2 = fmaxf(mx2, L[k]);
        }
        float e2[9]; float s2 = 0.f;
#pragma unroll
        for (int k = 0; k < 9; k++) { e2[k] = expf(L[k] - mx2); s2 += e2[k]; }
        float inv2 = 1.0f / s2;
#pragma unroll
        for (int k = 0; k < 9; k++) sPp[n * 12 + k] = e2[k] * inv2;
    }
    __syncthreads();

    // ---- epilogue: out[n,p,c] = sum_m P[n,m] * x[rm(m,p),c] ----
    // v double-buffered: load p+1 while computing p; P rows via LDS.128.
    float2* Ob = (float2*)out + (size_t)b * (HW81 * 256);

#pragma unroll
    for (int p = 0; p < 9; p++) {
        const int cur = p & 1;
        if (p < 8) {
#pragma unroll
            for (int m = 0; m < 9; m++)
                v[cur ^ 1][m] = Xb2[rowmap(m, p + 1) * 256 + tid];
        }
#pragma unroll
        for (int n = 0; n < 9; n++) {
            float4 w0 = *(const float4*)&sPp[n * 12 + 0];
            float4 w1 = *(const float4*)&sPp[n * 12 + 4];
            float  w2 = sPp[n * 12 + 8];
            float2 o = make_float2(0.f, 0.f);
            o.x += w0.x * v[cur][0].x;  o.y += w0.x * v[cur][0].y;
            o.x += w0.y * v[cur][1].x;  o.y += w0.y * v[cur][1].y;
            o.x += w0.z * v[cur][2].x;  o.y += w0.z * v[cur][2].y;
            o.x += w0.w * v[cur][3].x;  o.y += w0.w * v[cur][3].y;
            o.x += w1.x * v[cur][4].x;  o.y += w1.x * v[cur][4].y;
            o.x += w1.y * v[cur][5].x;  o.y += w1.y * v[cur][5].y;
            o.x += w1.z * v[cur][6].x;  o.y += w1.z * v[cur][6].y;
            o.x += w1.w * v[cur][7].x;  o.y += w1.w * v[cur][7].y;
            o.x += w2   * v[cur][8].x;  o.y += w2   * v[cur][8].y;
            Ob[rowmap(n, p) * 256 + tid] = o;
        }
    }
}

// ---------------------------------------------------------------------------
extern "C" void kernel_launch(void* const* d_in, const int* in_sizes, int n_in,
                              void* d_out, int out_size)
{
    const float* x   = (const float*)d_in[0];   // [2048, 9, 9, 512] fp32
    const float* Wf  = (const float*)d_in[1];   // [256, 512] fp32
    const float* bfc = (const float*)d_in[2];   // [256] fp32
    float* out = (float*)d_out;

    static bool init = false;
    if (!init) {
        cudaFuncSetAttribute(fused_kernel,
                             cudaFuncAttributeMaxDynamicSharedMemorySize,
                             SMEM_FLOATS * 4);
        init = true;
    }

    wprep_kernel<<<256, 512>>>(Wf);
    fused_kernel<<<BATCH, 256, SMEM_FLOATS * 4>>>(x, bfc, out);
}